// round 1
// baseline (speedup 1.0000x reference)
#include <cuda_runtime.h>

#define NS   524288
#define DIM  128
#define BG   128
#define HH   64
#define KK_  4
#define BH   (BG * HH)            /* 8192  */
#define NK   (NS * KK_)           /* 2097152 */
#define HUBF_ELEMS (BH * DIM)     /* 1048576 */

typedef unsigned long long ull;

// 256MB scratch for FFN output h[N, D]
__device__ float g_hbuf[(size_t)NS * DIM];

__device__ __forceinline__ ull pack2(float lo, float hi) {
    ull r;
    asm("mov.b64 %0, {%1, %2};" : "=l"(r) : "r"(__float_as_uint(lo)), "r"(__float_as_uint(hi)));
    return r;
}
__device__ __forceinline__ void unpack2(ull v, float& lo, float& hi) {
    unsigned a, b;
    asm("mov.b64 {%0, %1}, %2;" : "=r"(a), "=r"(b) : "l"(v));
    lo = __uint_as_float(a);
    hi = __uint_as_float(b);
}
__device__ __forceinline__ void ffma2(ull& d, ull a, ull b) {
    asm("fma.rn.f32x2 %0, %1, %2, %0;" : "+l"(d) : "l"(a), "l"(b));
}
__device__ __forceinline__ float gelu_exact(float v) {
    return 0.5f * v * (1.0f + erff(v * 0.7071067811865476f));
}

// ---------------------------------------------------------------------------
// K1: FFN  h = GELU(x@W1 + b1) @ W2 + b2   -> g_hbuf
// Tile: 64 spokes per block, 256 threads. Packed f32x2 FFMA accumulators.
// smem: x tile (32KB) + W slab (16KB) + gelu(h1) tile (64KB) = 112KB dynamic.
// ---------------------------------------------------------------------------
#define K1_SMEM ((64 * 128 + 16 * 256 + 64 * 256) * 4)

__global__ __launch_bounds__(256, 2)
void ffn_kernel(const float* __restrict__ x,
                const float* __restrict__ W1, const float* __restrict__ b1,
                const float* __restrict__ W2, const float* __restrict__ b2) {
    extern __shared__ float smem[];
    float* sx  = smem;                  // 64*128
    float* sw  = smem + 64 * 128;       // 16*256 (stage B reuses as 16*128)
    float* sh1 = sw + 16 * 256;         // 64*256

    const int tid  = threadIdx.x;
    const int warp = tid >> 5;
    const int nt   = tid & 31;
    const int r0   = warp * 8;          // 8 rows per warp
    const int c0   = nt * 4;
    const long base = (long)blockIdx.x * 64;

    // load x tile [64,128] (2048 float4, 8 per thread)
    {
        const float4* xg = (const float4*)(x + base * DIM);
        float4* sx4 = (float4*)sx;
#pragma unroll
        for (int t = 0; t < 8; t++) sx4[tid + t * 256] = xg[tid + t * 256];
    }

    // -------- stage A: h1 = x @ W1 ;  cols per thread: {c0..c0+3, 128+c0..128+c0+3}
    ull acc[8][4];
#pragma unroll
    for (int i = 0; i < 8; i++)
#pragma unroll
        for (int j = 0; j < 4; j++) acc[i][j] = pack2(0.f, 0.f);

    __syncthreads();

    for (int kk = 0; kk < 128; kk += 16) {
        // load W1 slab [16,256] (1024 float4, 4 per thread)
        const float4* wg = (const float4*)(W1 + kk * 256);
        float4* sw4 = (float4*)sw;
#pragma unroll
        for (int t = 0; t < 4; t++) sw4[tid + t * 256] = wg[tid + t * 256];
        __syncthreads();

        const ulonglong2* swu = (const ulonglong2*)sw;
#pragma unroll
        for (int k = 0; k < 16; k++) {
            ulonglong2 bA = swu[k * 64 + nt];        // cols c0..c0+3
            ulonglong2 bB = swu[k * 64 + 32 + nt];   // cols 128+c0..+3
#pragma unroll
            for (int i = 0; i < 8; i++) {
                float av = sx[(r0 + i) * 128 + kk + k];
                ull a2 = pack2(av, av);
                ffma2(acc[i][0], a2, bA.x);
                ffma2(acc[i][1], a2, bA.y);
                ffma2(acc[i][2], a2, bB.x);
                ffma2(acc[i][3], a2, bB.y);
            }
        }
        __syncthreads();
    }

    // stage A epilogue: + b1, GELU, store to sh1
    {
        float g0 = b1[c0], g1 = b1[c0 + 1], g2 = b1[c0 + 2], g3 = b1[c0 + 3];
        float p0 = b1[128 + c0], p1 = b1[128 + c0 + 1], p2 = b1[128 + c0 + 2], p3 = b1[128 + c0 + 3];
#pragma unroll
        for (int i = 0; i < 8; i++) {
            float a0, a1, a2v, a3, u0, u1, u2, u3;
            unpack2(acc[i][0], a0, a1);
            unpack2(acc[i][1], a2v, a3);
            unpack2(acc[i][2], u0, u1);
            unpack2(acc[i][3], u2, u3);
            float4 lo = make_float4(gelu_exact(a0 + g0), gelu_exact(a1 + g1),
                                    gelu_exact(a2v + g2), gelu_exact(a3 + g3));
            float4 hi = make_float4(gelu_exact(u0 + p0), gelu_exact(u1 + p1),
                                    gelu_exact(u2 + p2), gelu_exact(u3 + p3));
            *(float4*)&sh1[(r0 + i) * 256 + c0] = lo;
            *(float4*)&sh1[(r0 + i) * 256 + 128 + c0] = hi;
        }
    }
    __syncthreads();

    // -------- stage B: h2 = gelu_h1 @ W2 ;  cols per thread: c0..c0+3
    ull acc2[8][2];
#pragma unroll
    for (int i = 0; i < 8; i++) { acc2[i][0] = pack2(0.f, 0.f); acc2[i][1] = pack2(0.f, 0.f); }

    for (int kk = 0; kk < 256; kk += 16) {
        // load W2 slab [16,128] (512 float4, 2 per thread)
        const float4* wg = (const float4*)(W2 + kk * 128);
        float4* sw4 = (float4*)sw;
        sw4[tid]       = wg[tid];
        sw4[tid + 256] = wg[tid + 256];
        __syncthreads();

        const ulonglong2* swu = (const ulonglong2*)sw;
#pragma unroll
        for (int k = 0; k < 16; k++) {
            ulonglong2 bb = swu[k * 32 + nt];
#pragma unroll
            for (int i = 0; i < 8; i++) {
                float av = sh1[(r0 + i) * 256 + kk + k];
                ull a2 = pack2(av, av);
                ffma2(acc2[i][0], a2, bb.x);
                ffma2(acc2[i][1], a2, bb.y);
            }
        }
        __syncthreads();
    }

    // stage B epilogue: + b2, store to g_hbuf
    {
        float q0 = b2[c0], q1 = b2[c0 + 1], q2 = b2[c0 + 2], q3 = b2[c0 + 3];
#pragma unroll
        for (int i = 0; i < 8; i++) {
            float a0, a1, a2v, a3;
            unpack2(acc2[i][0], a0, a1);
            unpack2(acc2[i][1], a2v, a3);
            float4 v = make_float4(a0 + q0, a1 + q1, a2v + q2, a3 + q3);
            *(float4*)&g_hbuf[(base + r0 + i) * DIM + c0] = v;
        }
    }
}

// ---------------------------------------------------------------------------
// K2: scatter-mean per graph. batch_idx is sorted -> one block per graph.
// Thread d exclusively owns dim d of every hub row: no atomics on floats.
// ---------------------------------------------------------------------------
__global__ void scatter_kernel(const int* __restrict__ hub_idx,
                               const int* __restrict__ batch_idx,
                               float* __restrict__ hubf_out) {
    __shared__ float acc[HH][DIM];   // 32KB
    __shared__ int   cnt[HH];
    __shared__ int   srange[2];

    const int b = blockIdx.x;
    const int tid = threadIdx.x;     // 128 threads; tid == dim

    for (int i = tid; i < HH * DIM; i += 128) ((float*)acc)[i] = 0.f;
    if (tid < HH) cnt[tid] = 0;
    if (tid < 2) {
        int target = b + tid, lo = 0, hi = NS;
        while (lo < hi) { int mid = (lo + hi) >> 1; if (batch_idx[mid] < target) lo = mid + 1; else hi = mid; }
        srange[tid] = lo;
    }
    __syncthreads();

    const int s0 = srange[0], s1 = srange[1];

    for (int s = s0 + tid; s < s1; s += 128) atomicAdd(&cnt[hub_idx[s]], 1);

    for (int s = s0; s < s1; s++) {
        int hu = hub_idx[s];                          // broadcast load
        acc[hu][tid] += g_hbuf[(long)s * DIM + tid];  // coalesced, no atomics
    }
    __syncthreads();

    for (int h = 0; h < HH; h++) {
        float c = cnt[h] > 0 ? (float)cnt[h] : 1.0f;
        hubf_out[((long)b * HH + h) * DIM + tid] = acc[h][tid] / c;
    }
}

// ---------------------------------------------------------------------------
// K3: per-graph 64x64 kNN (top-4 smallest d2, tie-break lower index, self
// distance = 0 so self is first), then emit the edge index for the graph's
// contiguous spoke range.
// ---------------------------------------------------------------------------
__global__ void knn_edge_kernel(const int* __restrict__ hub_idx,
                                const int* __restrict__ batch_idx,
                                const float* __restrict__ hubf,
                                float* __restrict__ e0,
                                float* __restrict__ e1) {
    __shared__ float hf[HH][DIM + 1];   // +1 pad: conflict-free column reads
    __shared__ float d2row[8][HH];
    __shared__ int   knn[HH][KK_];
    __shared__ int   srange[2];

    const int b = blockIdx.x;
    const int tid = threadIdx.x;        // 256
    const int warp = tid >> 5, lane = tid & 31;

    for (int i = tid; i < HH * DIM; i += 256) {
        int h = i >> 7, d = i & 127;
        hf[h][d] = hubf[((long)b * HH + h) * DIM + d];
    }
    if (tid < 2) {
        int target = b + tid, lo = 0, hi = NS;
        while (lo < hi) { int mid = (lo + hi) >> 1; if (batch_idx[mid] < target) lo = mid + 1; else hi = mid; }
        srange[tid] = lo;
    }
    __syncthreads();

    for (int i = warp; i < HH; i += 8) {
        for (int jj = 0; jj < HH; jj += 32) {
            int j = jj + lane;
            float s = 0.f;
#pragma unroll
            for (int d = 0; d < DIM; d++) {
                float diff = hf[i][d] - hf[j][d];
                s = fmaf(diff, diff, s);
            }
            d2row[warp][j] = s;
        }
        float v0 = d2row[warp][lane], v1 = d2row[warp][lane + 32];
        int   i0 = lane,              i1 = lane + 32;
#pragma unroll
        for (int k = 0; k < KK_; k++) {
            float bv; int bi;
            if (v0 < v1 || (v0 == v1 && i0 < i1)) { bv = v0; bi = i0; }
            else                                   { bv = v1; bi = i1; }
#pragma unroll
            for (int off = 16; off; off >>= 1) {
                float ov = __shfl_xor_sync(0xffffffffu, bv, off);
                int   oi = __shfl_xor_sync(0xffffffffu, bi, off);
                if (ov < bv || (ov == bv && oi < bi)) { bv = ov; bi = oi; }
            }
            if (lane == 0) knn[i][k] = bi;
            if (i0 == bi) v0 = 3.4e38f;
            if (i1 == bi) v1 = 3.4e38f;
        }
    }
    __syncthreads();

    const int s0 = srange[0], s1 = srange[1];
    const int boff = b * HH;
    for (long idx = (long)s0 * KK_ + tid; idx < (long)s1 * KK_; idx += 256) {
        int s = (int)(idx >> 2);
        int k = (int)(idx & 3);
        int sh = hub_idx[s];
        e0[idx] = (float)s;
        e1[idx] = (float)(knn[sh][k] + boff);
    }
}

// ---------------------------------------------------------------------------
extern "C" void kernel_launch(void* const* d_in, const int* in_sizes, int n_in,
                              void* d_out, int out_size) {
    const float* x   = (const float*)d_in[0];
    const int*   hub = (const int*)d_in[1];
    const int*   bix = (const int*)d_in[2];
    const float* W1  = (const float*)d_in[3];
    const float* b1  = (const float*)d_in[4];
    const float* W2  = (const float*)d_in[5];
    const float* b2  = (const float*)d_in[6];

    float* out  = (float*)d_out;
    float* hubf = out;                       // [8192,128]
    float* e0   = out + HUBF_ELEMS;          // edge row 0
    float* e1   = out + HUBF_ELEMS + NK;     // edge row 1

    cudaFuncSetAttribute(ffn_kernel, cudaFuncAttributeMaxDynamicSharedMemorySize, K1_SMEM);

    ffn_kernel<<<NS / 64, 256, K1_SMEM>>>(x, W1, b1, W2, b2);
    scatter_kernel<<<BG, 128>>>(hub, bix, hubf);
    knn_edge_kernel<<<BG, 256>>>(hub, bix, hubf, e0, e1);
}

// round 3
// speedup vs baseline: 1.3289x; 1.3289x over previous
#include <cuda_runtime.h>
#include <cuda_bf16.h>
#include <cstdint>

#define NS   524288
#define DIM  128
#define BG   128
#define HH   64
#define KK_  4
#define BH   (BG * HH)
#define NK   (NS * KK_)
#define HUBF_ELEMS (BH * DIM)

#define TILES_PER_CTA 4
#define FFN_GRID (NS / 64 / TILES_PER_CTA)   /* 2048 */

// FFN output scratch
__device__ float g_hbuf[(size_t)NS * DIM];

// Prepped weights: bf16, transposed to [n][k], hi/lo split, XOR-swizzled.
// gW1: [split 2][n 256][k 128]  (65536 bf16 = 128KB)
__device__ __nv_bfloat16 gW1[65536];
// gW2: [slab 4][split 2][n 128][k 64]  (65536 bf16 = 128KB)
__device__ __nv_bfloat16 gW2[65536];

// SMEM byte offsets (ffn kernel)
#define OFF_W1H 0
#define OFF_W1L 65536
#define OFF_XH  131072
#define OFF_XL  147456
#define OFF_W2H 131072   /* reuses x region after GEMM1 */
#define OFF_W2L 147456
#define OFF_H1H 163840
#define OFF_H1L 196608
#define FFN_SMEM 229376

// ---------------------------------------------------------------------------
__device__ __forceinline__ uint32_t smem_u32(const void* p) {
    uint32_t a;
    asm("{ .reg .u64 t; cvta.to.shared.u64 t, %1; cvt.u32.u64 %0, t; }" : "=r"(a) : "l"(p));
    return a;
}
__device__ __forceinline__ void ldsm4(uint32_t addr, uint32_t r[4]) {
    asm volatile("ldmatrix.sync.aligned.m8n8.x4.shared.b16 {%0,%1,%2,%3}, [%4];"
                 : "=r"(r[0]), "=r"(r[1]), "=r"(r[2]), "=r"(r[3]) : "r"(addr));
}
__device__ __forceinline__ void mma16816(float c[4], const uint32_t a[4], uint32_t b0, uint32_t b1) {
    asm volatile("mma.sync.aligned.m16n8k16.row.col.f32.bf16.bf16.f32 "
                 "{%0,%1,%2,%3}, {%4,%5,%6,%7}, {%8,%9}, {%0,%1,%2,%3};"
                 : "+f"(c[0]), "+f"(c[1]), "+f"(c[2]), "+f"(c[3])
                 : "r"(a[0]), "r"(a[1]), "r"(a[2]), "r"(a[3]), "r"(b0), "r"(b1));
}
// A-operand ldmatrix address (16x16 tile at (m0, kb bytes)), row-major, swizzled
__device__ __forceinline__ uint32_t a_addr(uint32_t base, int stride, int m0, int kb, int lane) {
    int row = m0 + (lane & 15);
    int k = kb + ((lane >> 4) << 4);
    return base + row * stride + (uint32_t)(k ^ ((row & 7) << 4));
}
// B-operand ldmatrix address (two n8 tiles at (n0, kb)), Wt[n][k] layout, swizzled
__device__ __forceinline__ uint32_t b_addr(uint32_t base, int stride, int n0, int kb, int lane) {
    int row = n0 + (lane & 7) + ((lane & 16) >> 1);
    int k = kb + (((lane >> 3) & 1) << 4);
    return base + row * stride + (uint32_t)(k ^ ((row & 7) << 4));
}
__device__ __forceinline__ float gelu_exact(float v) {
    return 0.5f * v * (1.0f + erff(v * 0.7071067811865476f));
}
__device__ __forceinline__ uint32_t pack_bf2(__nv_bfloat16 a, __nv_bfloat16 b) {
    __nv_bfloat162 t; t.x = a; t.y = b;
    return *(uint32_t*)&t;
}

// ---------------------------------------------------------------------------
// K0: weight prep — transpose, hi/lo split, XOR swizzle
// ---------------------------------------------------------------------------
__global__ void prep_weights(const float* __restrict__ W1, const float* __restrict__ W2) {
    int tid = threadIdx.x + blockIdx.x * blockDim.x;
    int stride = blockDim.x * gridDim.x;
    for (int i = tid; i < 65536; i += stride) {
        int split = i >> 15, r = i & 32767, n = r >> 7, k = r & 127;
        float v = W1[k * 256 + n];
        __nv_bfloat16 hi = __float2bfloat16(v);
        __nv_bfloat16 val = split ? __float2bfloat16(v - __bfloat162float(hi)) : hi;
        uint32_t off = (uint32_t)(n * 256) + (uint32_t)((k * 2) ^ ((n & 7) << 4));
        *(__nv_bfloat16*)((char*)gW1 + (size_t)split * 65536 + off) = val;
    }
    for (int i = tid; i < 65536; i += stride) {
        int s = i >> 14, r = i & 16383, split = r >> 13, rr = r & 8191, n = rr >> 6, k = rr & 63;
        float v = W2[(s * 64 + k) * 128 + n];
        __nv_bfloat16 hi = __float2bfloat16(v);
        __nv_bfloat16 val = split ? __float2bfloat16(v - __bfloat162float(hi)) : hi;
        uint32_t off = (uint32_t)(n * 128) + (uint32_t)((k * 2) ^ ((n & 7) << 4));
        *(__nv_bfloat16*)((char*)gW2 + (size_t)s * 32768 + (size_t)split * 16384 + off) = val;
    }
}

// ---------------------------------------------------------------------------
// K1: FFN via mma.sync bf16 (hi/lo split, 3 terms). 64 rows per tile,
// TILES_PER_CTA tiles per CTA, W1 resident in smem, W2 slab-streamed.
// 256 threads = 8 warps: GEMM1 warp grid 2Mx4N (tile 32x64),
//                        GEMM2 warp grid 2Mx4N (tile 32x32).
// ---------------------------------------------------------------------------
__global__ void __launch_bounds__(256)
ffn_mma(const float* __restrict__ x,
        const float* __restrict__ b1, const float* __restrict__ b2) {
    extern __shared__ char sm[];
    const uint32_t sb = smem_u32(sm);
    const int tid = threadIdx.x;
    const int wid = tid >> 5;
    const int lane = tid & 31;
    const int wm = wid & 1;        // 0-1
    const int wn = wid >> 1;       // 0-3

    // load W1 (hi+lo) once: 131072 B = 8192 uint4
    {
        const uint4* src = (const uint4*)gW1;
        uint4* dst = (uint4*)(sm + OFF_W1H);
#pragma unroll 8
        for (int i = tid; i < 8192; i += 256) dst[i] = src[i];
    }

    for (int t = 0; t < TILES_PER_CTA; t++) {
        const int tile = blockIdx.x * TILES_PER_CTA + t;
        const size_t rowbase = (size_t)tile * 64;

        __syncthreads();   // protect x/W2-slab region + h1 from previous tile

        // ---- load x tile [64,128] f32 -> bf16 hi/lo, swizzled ----
        {
            const float4* xg = (const float4*)(x + rowbase * DIM);
#pragma unroll
            for (int ii = 0; ii < 8; ii++) {
                int i = tid + ii * 256;
                float4 v = xg[i];
                int row = i >> 5, k = (i & 31) * 4;
                __nv_bfloat16 h0 = __float2bfloat16(v.x), h1v = __float2bfloat16(v.y);
                __nv_bfloat16 h2 = __float2bfloat16(v.z), h3 = __float2bfloat16(v.w);
                __nv_bfloat16 l0 = __float2bfloat16(v.x - __bfloat162float(h0));
                __nv_bfloat16 l1 = __float2bfloat16(v.y - __bfloat162float(h1v));
                __nv_bfloat16 l2 = __float2bfloat16(v.z - __bfloat162float(h2));
                __nv_bfloat16 l3 = __float2bfloat16(v.w - __bfloat162float(h3));
                uint32_t off = (uint32_t)((k * 2) ^ ((row & 7) << 4)) + row * 256;
                *(uint2*)(sm + OFF_XH + off) = make_uint2(pack_bf2(h0, h1v), pack_bf2(h2, h3));
                *(uint2*)(sm + OFF_XL + off) = make_uint2(pack_bf2(l0, l1), pack_bf2(l2, l3));
            }
        }
        __syncthreads();

        // ---- GEMM1: [64,128] x [128,256] -> acc warp tile 32x64 ----
        float acc[2][8][4];
#pragma unroll
        for (int a = 0; a < 2; a++)
#pragma unroll
            for (int b = 0; b < 8; b++)
#pragma unroll
                for (int c = 0; c < 4; c++) acc[a][b][c] = 0.f;

#pragma unroll
        for (int ks = 0; ks < 8; ks++) {
            const int kb = ks * 32;
            uint32_t ah[2][4], al[2][4];
#pragma unroll
            for (int mt = 0; mt < 2; mt++) {
                ldsm4(a_addr(sb + OFF_XH, 256, wm * 32 + mt * 16, kb, lane), ah[mt]);
                ldsm4(a_addr(sb + OFF_XL, 256, wm * 32 + mt * 16, kb, lane), al[mt]);
            }
#pragma unroll
            for (int ntp = 0; ntp < 4; ntp++) {
                const int n0 = wn * 64 + ntp * 16;
                uint32_t bh[4], bl[4];
                ldsm4(b_addr(sb + OFF_W1H, 256, n0, kb, lane), bh);
                ldsm4(b_addr(sb + OFF_W1L, 256, n0, kb, lane), bl);
#pragma unroll
                for (int mt = 0; mt < 2; mt++) {
                    mma16816(acc[mt][ntp * 2],     ah[mt], bh[0], bh[1]);
                    mma16816(acc[mt][ntp * 2],     al[mt], bh[0], bh[1]);
                    mma16816(acc[mt][ntp * 2],     ah[mt], bl[0], bl[1]);
                    mma16816(acc[mt][ntp * 2 + 1], ah[mt], bh[2], bh[3]);
                    mma16816(acc[mt][ntp * 2 + 1], al[mt], bh[2], bh[3]);
                    mma16816(acc[mt][ntp * 2 + 1], ah[mt], bl[2], bl[3]);
                }
            }
        }

        // ---- Epilogue 1: +b1, GELU, split -> h1 (smem) ----
#pragma unroll
        for (int nt = 0; nt < 8; nt++) {
            const int col = wn * 64 + nt * 8 + (lane & 3) * 2;
            const float2 bb = *(const float2*)&b1[col];
#pragma unroll
            for (int mt = 0; mt < 2; mt++) {
                const int r = wm * 32 + mt * 16 + (lane >> 2);
#pragma unroll
                for (int h = 0; h < 2; h++) {
                    const int rr = r + h * 8;
                    float v0 = gelu_exact(acc[mt][nt][h * 2]     + bb.x);
                    float v1 = gelu_exact(acc[mt][nt][h * 2 + 1] + bb.y);
                    __nv_bfloat16 h0 = __float2bfloat16(v0), h1v = __float2bfloat16(v1);
                    __nv_bfloat16 l0 = __float2bfloat16(v0 - __bfloat162float(h0));
                    __nv_bfloat16 l1 = __float2bfloat16(v1 - __bfloat162float(h1v));
                    uint32_t off = rr * 512 + (uint32_t)((col * 2) ^ ((rr & 7) << 4));
                    *(uint32_t*)(sm + OFF_H1H + off) = pack_bf2(h0, h1v);
                    *(uint32_t*)(sm + OFF_H1L + off) = pack_bf2(l0, l1);
                }
            }
        }
        __syncthreads();   // h1 visible; x reads done -> W2 slabs may overwrite

        // ---- GEMM2: [64,256] x [256,128], W2 in 4 k-slabs of 64 ----
        float acc2[2][4][4];
#pragma unroll
        for (int a = 0; a < 2; a++)
#pragma unroll
            for (int b = 0; b < 4; b++)
#pragma unroll
                for (int c = 0; c < 4; c++) acc2[a][b][c] = 0.f;

        for (int s = 0; s < 4; s++) {
            {
                const uint4* src = (const uint4*)((const char*)gW2 + (size_t)s * 32768);
                uint4* dst = (uint4*)(sm + OFF_W2H);
#pragma unroll
                for (int i = tid; i < 2048; i += 256) dst[i] = src[i];
            }
            __syncthreads();
#pragma unroll
            for (int ks = 0; ks < 4; ks++) {
                const int kb = ks * 32;          // within slab (bytes)
                const int akb = s * 128 + kb;    // within h1 (bytes)
                uint32_t ah[2][4], al[2][4];
#pragma unroll
                for (int mt = 0; mt < 2; mt++) {
                    ldsm4(a_addr(sb + OFF_H1H, 512, wm * 32 + mt * 16, akb, lane), ah[mt]);
                    ldsm4(a_addr(sb + OFF_H1L, 512, wm * 32 + mt * 16, akb, lane), al[mt]);
                }
#pragma unroll
                for (int ntp = 0; ntp < 2; ntp++) {
                    const int n0 = wn * 32 + ntp * 16;
                    uint32_t bh[4], bl[4];
                    ldsm4(b_addr(sb + OFF_W2H, 128, n0, kb, lane), bh);
                    ldsm4(b_addr(sb + OFF_W2L, 128, n0, kb, lane), bl);
#pragma unroll
                    for (int mt = 0; mt < 2; mt++) {
                        mma16816(acc2[mt][ntp * 2],     ah[mt], bh[0], bh[1]);
                        mma16816(acc2[mt][ntp * 2],     al[mt], bh[0], bh[1]);
                        mma16816(acc2[mt][ntp * 2],     ah[mt], bl[0], bl[1]);
                        mma16816(acc2[mt][ntp * 2 + 1], ah[mt], bh[2], bh[3]);
                        mma16816(acc2[mt][ntp * 2 + 1], al[mt], bh[2], bh[3]);
                        mma16816(acc2[mt][ntp * 2 + 1], ah[mt], bl[2], bl[3]);
                    }
                }
            }
            __syncthreads();   // slab reads done before next overwrite
        }

        // ---- Epilogue 2: +b2 -> g_hbuf ----
#pragma unroll
        for (int nt = 0; nt < 4; nt++) {
            const int col = wn * 32 + nt * 8 + (lane & 3) * 2;
            const float2 bb = *(const float2*)&b2[col];
#pragma unroll
            for (int mt = 0; mt < 2; mt++) {
                const int r = wm * 32 + mt * 16 + (lane >> 2);
#pragma unroll
                for (int h = 0; h < 2; h++) {
                    const int rr = r + h * 8;
                    float2 v = make_float2(acc2[mt][nt][h * 2] + bb.x,
                                           acc2[mt][nt][h * 2 + 1] + bb.y);
                    *(float2*)&g_hbuf[(rowbase + rr) * DIM + col] = v;
                }
            }
        }
    }
}

// ---------------------------------------------------------------------------
// K2: scatter-mean per graph (batch_idx sorted, one block per graph)
// ---------------------------------------------------------------------------
__global__ void scatter_kernel(const int* __restrict__ hub_idx,
                               const int* __restrict__ batch_idx,
                               float* __restrict__ hubf_out) {
    __shared__ float acc[HH][DIM];
    __shared__ int   cnt[HH];
    __shared__ int   srange[2];

    const int b = blockIdx.x;
    const int tid = threadIdx.x;   // 128 threads; tid == dim

    for (int i = tid; i < HH * DIM; i += 128) ((float*)acc)[i] = 0.f;
    if (tid < HH) cnt[tid] = 0;
    if (tid < 2) {
        int target = b + tid, lo = 0, hi = NS;
        while (lo < hi) { int mid = (lo + hi) >> 1; if (batch_idx[mid] < target) lo = mid + 1; else hi = mid; }
        srange[tid] = lo;
    }
    __syncthreads();

    const int s0 = srange[0], s1 = srange[1];
    for (int s = s0 + tid; s < s1; s += 128) atomicAdd(&cnt[hub_idx[s]], 1);
    for (int s = s0; s < s1; s++) {
        int hu = hub_idx[s];
        acc[hu][tid] += g_hbuf[(size_t)s * DIM + tid];
    }
    __syncthreads();

    for (int h = 0; h < HH; h++) {
        float c = cnt[h] > 0 ? (float)cnt[h] : 1.0f;
        hubf_out[((size_t)b * HH + h) * DIM + tid] = acc[h][tid] / c;
    }
}

// ---------------------------------------------------------------------------
// K3: per-graph 64x64 kNN (top-4 min d2, tie-break lower index) + edge emit
// ---------------------------------------------------------------------------
__global__ void knn_edge_kernel(const int* __restrict__ hub_idx,
                                const int* __restrict__ batch_idx,
                                const float* __restrict__ hubf,
                                float* __restrict__ e0,
                                float* __restrict__ e1) {
    __shared__ float hf[HH][DIM + 1];
    __shared__ float d2row[8][HH];
    __shared__ int   knn[HH][KK_];
    __shared__ int   srange[2];

    const int b = blockIdx.x;
    const int tid = threadIdx.x;   // 256
    const int warp = tid >> 5, lane = tid & 31;

    for (int i = tid; i < HH * DIM; i += 256) {
        int h = i >> 7, d = i & 127;
        hf[h][d] = hubf[((size_t)b * HH + h) * DIM + d];
    }
    if (tid < 2) {
        int target = b + tid, lo = 0, hi = NS;
        while (lo < hi) { int mid = (lo + hi) >> 1; if (batch_idx[mid] < target) lo = mid + 1; else hi = mid; }
        srange[tid] = lo;
    }
    __syncthreads();

    for (int i = warp; i < HH; i += 8) {
        for (int jj = 0; jj < HH; jj += 32) {
            int j = jj + lane;
            float s = 0.f;
#pragma unroll
            for (int d = 0; d < DIM; d++) {
                float diff = hf[i][d] - hf[j][d];
                s = fmaf(diff, diff, s);
            }
            d2row[warp][j] = s;
        }
        float v0 = d2row[warp][lane], v1 = d2row[warp][lane + 32];
        int   i0 = lane,              i1 = lane + 32;
#pragma unroll
        for (int k = 0; k < KK_; k++) {
            float bv; int bi;
            if (v0 < v1 || (v0 == v1 && i0 < i1)) { bv = v0; bi = i0; }
            else                                   { bv = v1; bi = i1; }
#pragma unroll
            for (int off = 16; off; off >>= 1) {
                float ov = __shfl_xor_sync(0xffffffffu, bv, off);
                int   oi = __shfl_xor_sync(0xffffffffu, bi, off);
                if (ov < bv || (ov == bv && oi < bi)) { bv = ov; bi = oi; }
            }
            if (lane == 0) knn[i][k] = bi;
            if (i0 == bi) v0 = 3.4e38f;
            if (i1 == bi) v1 = 3.4e38f;
        }
    }
    __syncthreads();

    const int s0 = srange[0], s1 = srange[1];
    const int boff = b * HH;
    for (long idx = (long)s0 * KK_ + tid; idx < (long)s1 * KK_; idx += 256) {
        int s = (int)(idx >> 2);
        int k = (int)(idx & 3);
        int sh = hub_idx[s];
        e0[idx] = (float)s;
        e1[idx] = (float)(knn[sh][k] + boff);
    }
}

// ---------------------------------------------------------------------------
extern "C" void kernel_launch(void* const* d_in, const int* in_sizes, int n_in,
                              void* d_out, int out_size) {
    const float* x   = (const float*)d_in[0];
    const int*   hub = (const int*)d_in[1];
    const int*   bix = (const int*)d_in[2];
    const float* W1  = (const float*)d_in[3];
    const float* b1  = (const float*)d_in[4];
    const float* W2  = (const float*)d_in[5];
    const float* b2  = (const float*)d_in[6];

    float* out  = (float*)d_out;
    float* hubf = out;
    float* e0   = out + HUBF_ELEMS;
    float* e1   = out + HUBF_ELEMS + NK;

    cudaFuncSetAttribute(ffn_mma, cudaFuncAttributeMaxDynamicSharedMemorySize, FFN_SMEM);

    prep_weights<<<64, 256>>>(W1, W2);
    ffn_mma<<<FFN_GRID, 256, FFN_SMEM>>>(x, b1, b2);
    scatter_kernel<<<BG, 128>>>(hub, bix, hubf);
    knn_edge_kernel<<<BG, 256>>>(hub, bix, hubf, e0, e1);
}